// round 5
// baseline (speedup 1.0000x reference)
#include <cuda_runtime.h>
#include <math.h>

#define ST     65
#define MSZ    (64*ST)
#define EPSV   1e-10f
#define NSWEEP 8

// ---------------------------------------------------------------------------
// round-robin tournament pairing: 63 rounds x 32 disjoint pairs covering all
// unordered pairs of {0..63}
// ---------------------------------------------------------------------------
__device__ __forceinline__ int2 pair_for(int r, int k) {
    int p, q;
    if (k == 0) {
        p = 63;
        q = r;                 // r in [0,62] already < 63
    } else {
        p = r + k;       if (p >= 63) p -= 63;
        q = r + 63 - k;  if (q >= 63) q -= 63;
    }
    if (p > q) { int t = p; p = q; q = t; }
    return make_int2(p, q);
}

// ---------------------------------------------------------------------------
// parallel cyclic Jacobi eigensolver for symmetric 64x64 in SMEM.
// Fixed NSWEEP sweeps — no data-dependent control flow, no early exit.
// On exit: diag(A) = eigenvalues, V = eigenvectors (columns).
// 256 threads.
// ---------------------------------------------------------------------------
__device__ void jacobi64(float* __restrict__ A, float* __restrict__ V, int tid,
                         int* __restrict__ spq, float2* __restrict__ scs)
{
    // V = I
    #pragma unroll
    for (int it = 0; it < 16; ++it) {
        int idx = tid + it * 256;
        int i = idx >> 6, j = idx & 63;
        V[i * ST + j] = (i == j) ? 1.f : 0.f;
    }
    __syncthreads();

    #pragma unroll 1
    for (int sweep = 0; sweep < NSWEEP; ++sweep) {
        #pragma unroll 1
        for (int r = 0; r < 63; ++r) {
            // --- rotation generation (warp 0 only) ---
            if (tid < 32) {
                int2 pq = pair_for(r, tid);
                int p = pq.x, q = pq.y;
                float app = A[p * ST + p];
                float aqq = A[q * ST + q];
                float apq = A[p * ST + q];
                float c = 1.f, s = 0.f;
                if (apq * apq > 1e-10f * app * aqq) {
                    float tau = (aqq - app) / (2.f * apq);
                    float tf  = copysignf(1.f, tau) /
                                (fabsf(tau) + sqrtf(fmaf(tau, tau, 1.f)));
                    c = 1.f / sqrtf(fmaf(tf, tf, 1.f));
                    s = tf * c;
                }
                spq[tid] = p | (q << 8);
                scs[tid] = make_float2(c, s);
            }
            __syncthreads();

            // --- row phase: A <- J^T A ---
            // w = tid + it*256 : k = w>>6 (uniform per warp), j = w&63
            #pragma unroll
            for (int it = 0; it < 8; ++it) {
                int w = tid + it * 256;
                int k = w >> 6, j = w & 63;
                float2 cs = scs[k];
                if (cs.y != 0.f) {
                    int pq = spq[k];
                    int p = pq & 255, q = pq >> 8;
                    float ap = A[p * ST + j], aq = A[q * ST + j];
                    A[p * ST + j] = fmaf(cs.x, ap, -cs.y * aq);
                    A[q * ST + j] = fmaf(cs.y, ap,  cs.x * aq);
                }
            }
            __syncthreads();

            // --- col phase: A <- A J, V <- V J ---
            #pragma unroll
            for (int it = 0; it < 8; ++it) {
                int w = tid + it * 256;
                int k = w >> 6, i = w & 63;
                float2 cs = scs[k];
                if (cs.y != 0.f) {
                    int pq = spq[k];
                    int p = pq & 255, q = pq >> 8;
                    int ip = i * ST + p, iq = i * ST + q;
                    float ap = A[ip], aq = A[iq];
                    A[ip] = fmaf(cs.x, ap, -cs.y * aq);
                    A[iq] = fmaf(cs.y, ap,  cs.x * aq);
                    float vp = V[ip], vq = V[iq];
                    V[ip] = fmaf(cs.x, vp, -cs.y * vq);
                    V[iq] = fmaf(cs.y, vp,  cs.x * vq);
                }
            }
            __syncthreads();
        }
    }
}

// ---------------------------------------------------------------------------
// 64x64x64 SMEM GEMM, 256 threads, 4x4 register tile per thread.
// MODE 0: C = A*B    MODE 1: C = A*B^T    MODE 2: C = A^T*B
// ---------------------------------------------------------------------------
template<int MODE>
__device__ void gemm64(const float* __restrict__ A, const float* __restrict__ B,
                       float* __restrict__ C, int tid)
{
    const int r0 = (tid >> 4) * 4;
    const int c0 = (tid & 15) * 4;
    float acc[4][4];
    #pragma unroll
    for (int i = 0; i < 4; ++i)
        #pragma unroll
        for (int j = 0; j < 4; ++j) acc[i][j] = 0.f;

    #pragma unroll 4
    for (int k = 0; k < 64; ++k) {
        float a[4], b[4];
        #pragma unroll
        for (int i = 0; i < 4; ++i)
            a[i] = (MODE == 2) ? A[k * ST + r0 + i] : A[(r0 + i) * ST + k];
        #pragma unroll
        for (int j = 0; j < 4; ++j)
            b[j] = (MODE == 1) ? B[(c0 + j) * ST + k] : B[k * ST + c0 + j];
        #pragma unroll
        for (int i = 0; i < 4; ++i)
            #pragma unroll
            for (int j = 0; j < 4; ++j)
                acc[i][j] = fmaf(a[i], b[j], acc[i][j]);
    }
    #pragma unroll
    for (int i = 0; i < 4; ++i)
        #pragma unroll
        for (int j = 0; j < 4; ++j)
            C[(r0 + i) * ST + c0 + j] = acc[i][j];
}

// final M = F * F^T written straight to GMEM (float4 rows)
__device__ void gemm_ffT_out(const float* __restrict__ F,
                             float* __restrict__ out, int tid)
{
    const int r0 = (tid >> 4) * 4;
    const int c0 = (tid & 15) * 4;
    float acc[4][4];
    #pragma unroll
    for (int i = 0; i < 4; ++i)
        #pragma unroll
        for (int j = 0; j < 4; ++j) acc[i][j] = 0.f;

    #pragma unroll 4
    for (int k = 0; k < 64; ++k) {
        float a[4], b[4];
        #pragma unroll
        for (int i = 0; i < 4; ++i) a[i] = F[(r0 + i) * ST + k];
        #pragma unroll
        for (int j = 0; j < 4; ++j) b[j] = F[(c0 + j) * ST + k];
        #pragma unroll
        for (int i = 0; i < 4; ++i)
            #pragma unroll
            for (int j = 0; j < 4; ++j)
                acc[i][j] = fmaf(a[i], b[j], acc[i][j]);
    }
    #pragma unroll
    for (int i = 0; i < 4; ++i) {
        float4 v = make_float4(acc[i][0], acc[i][1], acc[i][2], acc[i][3]);
        *reinterpret_cast<float4*>(out + (r0 + i) * 64 + c0) = v;
    }
}

// ---------------------------------------------------------------------------
// main kernel: one CTA per batch element
// ---------------------------------------------------------------------------
__global__ void __launch_bounds__(256)
spd_frechet_kernel(const float* __restrict__ xg,
                   const float* __restrict__ wg,
                   float* __restrict__ outg, int nsteps)
{
    extern __shared__ float sm[];
    float* MA  = sm;             // Jacobi working matrix / temps
    float* MV  = sm + MSZ;       // eigenvectors / temps
    float* MF  = sm + 2 * MSZ;   // F
    float* MFi = sm + 3 * MSZ;   // F^{-1}

    __shared__ int    spq[32];
    __shared__ float2 scs[32];
    __shared__ float  sd1[64], sd2[64];
    __shared__ float  st_[32];

    const int tid = threadIdx.x;
    const int b   = blockIdx.x;

    // t_n = w_n / cumsum(w)_n  (normalization of w cancels; w = weight^2)
    if (tid == 0) {
        float cum = 0.f;
        for (int k = 0; k < nsteps && k < 32; ++k) {
            float w2 = wg[k] * wg[k];
            cum += w2;
            st_[k] = w2 / cum;
        }
    }

    const float4* xb = reinterpret_cast<const float4*>(
        xg + (size_t)b * nsteps * 4096);

    // ---- load X_0 into MA ----
    #pragma unroll
    for (int it = 0; it < 4; ++it) {
        int idx4 = tid + it * 256;
        float4 v = xb[idx4];
        int flat = idx4 * 4;
        int i = flat >> 6, j = flat & 63;
        MA[i * ST + j + 0] = v.x;
        MA[i * ST + j + 1] = v.y;
        MA[i * ST + j + 2] = v.z;
        MA[i * ST + j + 3] = v.w;
    }
    __syncthreads();

    // ---- init: eigh(X0) -> F = V sqrt(E), Finv = E^{-1/2} V^T ----
    jacobi64(MA, MV, tid, spq, scs);
    if (tid < 64) {
        float e = fmaxf(MA[tid * ST + tid], EPSV);
        float s = sqrtf(e);
        sd1[tid] = s;
        sd2[tid] = 1.f / s;
    }
    __syncthreads();
    #pragma unroll
    for (int it = 0; it < 16; ++it) {
        int idx = tid + it * 256;
        int i = idx >> 6, j = idx & 63;
        MF[i * ST + j]  = MV[i * ST + j] * sd1[j];
        MFi[i * ST + j] = sd2[i] * MV[j * ST + i];
    }
    __syncthreads();

    // ---- scan steps n = 1..nsteps-1 ----
    #pragma unroll 1
    for (int n = 1; n < nsteps; ++n) {
        // load X_n into MA
        #pragma unroll
        for (int it = 0; it < 4; ++it) {
            int idx4 = tid + it * 256;
            float4 v = xb[n * 1024 + idx4];
            int flat = idx4 * 4;
            int i = flat >> 6, j = flat & 63;
            MA[i * ST + j + 0] = v.x;
            MA[i * ST + j + 1] = v.y;
            MA[i * ST + j + 2] = v.z;
            MA[i * ST + j + 3] = v.w;
        }
        __syncthreads();

        gemm64<0>(MFi, MA, MV, tid);   // T = Finv * X
        __syncthreads();
        gemm64<1>(MV, MFi, MA, tid);   // S = T * Finv^T
        __syncthreads();

        // symmetrize S
        float tmp[16];
        #pragma unroll
        for (int it = 0; it < 16; ++it) {
            int idx = tid + it * 256;
            int i = idx >> 6, j = idx & 63;
            tmp[it] = 0.5f * (MA[i * ST + j] + MA[j * ST + i]);
        }
        __syncthreads();
        #pragma unroll
        for (int it = 0; it < 16; ++it) {
            int idx = tid + it * 256;
            int i = idx >> 6, j = idx & 63;
            MA[i * ST + j] = tmp[it];
        }
        __syncthreads();

        // eigh(S)
        jacobi64(MA, MV, tid, spq, scs);

        // d1 = E^{t/2}, d2 = E^{-t/2}
        float ht = 0.5f * st_[n];
        if (tid < 64) {
            float e = fmaxf(MA[tid * ST + tid], EPSV);
            float p = powf(e, ht);
            sd1[tid] = p;
            sd2[tid] = 1.f / p;
        }
        __syncthreads();

        // F' = (F * V2) * diag(d1)
        gemm64<0>(MF, MV, MA, tid);
        __syncthreads();
        #pragma unroll
        for (int it = 0; it < 16; ++it) {
            int idx = tid + it * 256;
            int i = idx >> 6, j = idx & 63;
            MF[i * ST + j] = MA[i * ST + j] * sd1[j];
        }
        __syncthreads();

        // Finv' = diag(d2) * (V2^T * Finv)
        gemm64<2>(MV, MFi, MA, tid);
        __syncthreads();
        #pragma unroll
        for (int it = 0; it < 16; ++it) {
            int idx = tid + it * 256;
            int i = idx >> 6, j = idx & 63;
            MFi[i * ST + j] = sd2[i] * MA[i * ST + j];
        }
        __syncthreads();
    }

    // ---- M = F * F^T -> output ----
    gemm_ffT_out(MF, outg + (size_t)b * 4096, tid);
}

// ---------------------------------------------------------------------------
extern "C" void kernel_launch(void* const* d_in, const int* in_sizes, int n_in,
                              void* d_out, int out_size)
{
    const float* x = (const float*)d_in[0];
    const float* w = (const float*)d_in[1];
    int sx = in_sizes[0], sw = in_sizes[1];
    if (n_in >= 2 && sx < sw) {  // defensive: x is the big tensor
        const float* t = x; x = w; w = t;
        int ts = sx; sx = sw; sw = ts;
    }
    const int nsteps = sw;                    // N = 16
    const int B = sx / (nsteps * 64 * 64);    // 512
    float* out = (float*)d_out;

    const int smem_bytes = 4 * MSZ * sizeof(float);  // 66,560 B
    cudaFuncSetAttribute(spd_frechet_kernel,
                         cudaFuncAttributeMaxDynamicSharedMemorySize,
                         smem_bytes);
    spd_frechet_kernel<<<B, 256, smem_bytes>>>(x, w, out, nsteps);
}

// round 9
// speedup vs baseline: 1.0493x; 1.0493x over previous
#include <cuda_runtime.h>
#include <math.h>

#define ST     65
#define MSZ    (64*ST)
#define EPSV   1e-10f
#define NSWEEP 7

// ---------------------------------------------------------------------------
// round-robin tournament pairing: 63 rounds x 32 disjoint pairs covering all
// unordered pairs of {0..63}
// ---------------------------------------------------------------------------
__device__ __forceinline__ int2 pair_for(int r, int k) {
    int p, q;
    if (k == 0) {
        p = 63;
        q = r;                 // r in [0,62] already < 63
    } else {
        p = r + k;       if (p >= 63) p -= 63;
        q = r + 63 - k;  if (q >= 63) q -= 63;
    }
    if (p > q) { int t = p; p = q; q = t; }
    return make_int2(p, q);
}

// ---------------------------------------------------------------------------
// parallel cyclic Jacobi eigensolver for symmetric 64x64 in SMEM.
// Fixed NSWEEP sweeps — no data-dependent control flow, no early exit.
// On exit: diag(A) = eigenvalues, V = eigenvectors (columns).
// 256 threads.
// ---------------------------------------------------------------------------
__device__ void jacobi64(float* __restrict__ A, float* __restrict__ V, int tid,
                         int* __restrict__ spq, float2* __restrict__ scs)
{
    // V = I
    #pragma unroll
    for (int it = 0; it < 16; ++it) {
        int idx = tid + it * 256;
        int i = idx >> 6, j = idx & 63;
        V[i * ST + j] = (i == j) ? 1.f : 0.f;
    }
    __syncthreads();

    #pragma unroll 1
    for (int sweep = 0; sweep < NSWEEP; ++sweep) {
        #pragma unroll 1
        for (int r = 0; r < 63; ++r) {
            // --- rotation generation (warp 0 only) ---
            if (tid < 32) {
                int2 pq = pair_for(r, tid);
                int p = pq.x, q = pq.y;
                float app = A[p * ST + p];
                float aqq = A[q * ST + q];
                float apq = A[p * ST + q];
                float c = 1.f, s = 0.f;
                if (apq * apq > 1e-10f * app * aqq) {
                    float tau = (aqq - app) / (2.f * apq);
                    float tf  = copysignf(1.f, tau) /
                                (fabsf(tau) + sqrtf(fmaf(tau, tau, 1.f)));
                    c = 1.f / sqrtf(fmaf(tf, tf, 1.f));
                    s = tf * c;
                }
                spq[tid] = p | (q << 8);
                scs[tid] = make_float2(c, s);
            }
            __syncthreads();

            // --- row phase: A <- J^T A ---
            // w = tid + it*256 : k = w>>6 (uniform per warp), j = w&63
            #pragma unroll
            for (int it = 0; it < 8; ++it) {
                int w = tid + it * 256;
                int k = w >> 6, j = w & 63;
                float2 cs = scs[k];
                if (cs.y != 0.f) {
                    int pq = spq[k];
                    int p = pq & 255, q = pq >> 8;
                    float ap = A[p * ST + j], aq = A[q * ST + j];
                    A[p * ST + j] = fmaf(cs.x, ap, -cs.y * aq);
                    A[q * ST + j] = fmaf(cs.y, ap,  cs.x * aq);
                }
            }
            __syncthreads();

            // --- col phase: A <- A J, V <- V J ---
            #pragma unroll
            for (int it = 0; it < 8; ++it) {
                int w = tid + it * 256;
                int k = w >> 6, i = w & 63;
                float2 cs = scs[k];
                if (cs.y != 0.f) {
                    int pq = spq[k];
                    int p = pq & 255, q = pq >> 8;
                    int ip = i * ST + p, iq = i * ST + q;
                    float ap = A[ip], aq = A[iq];
                    A[ip] = fmaf(cs.x, ap, -cs.y * aq);
                    A[iq] = fmaf(cs.y, ap,  cs.x * aq);
                    float vp = V[ip], vq = V[iq];
                    V[ip] = fmaf(cs.x, vp, -cs.y * vq);
                    V[iq] = fmaf(cs.y, vp,  cs.x * vq);
                }
            }
            __syncthreads();
        }
    }
}

// ---------------------------------------------------------------------------
// 64x64x64 SMEM GEMM, 256 threads, 4x4 register tile per thread.
// MODE 0: C = A*B    MODE 1: C = A*B^T    MODE 2: C = A^T*B
// ---------------------------------------------------------------------------
template<int MODE>
__device__ void gemm64(const float* __restrict__ A, const float* __restrict__ B,
                       float* __restrict__ C, int tid)
{
    const int r0 = (tid >> 4) * 4;
    const int c0 = (tid & 15) * 4;
    float acc[4][4];
    #pragma unroll
    for (int i = 0; i < 4; ++i)
        #pragma unroll
        for (int j = 0; j < 4; ++j) acc[i][j] = 0.f;

    #pragma unroll 4
    for (int k = 0; k < 64; ++k) {
        float a[4], b[4];
        #pragma unroll
        for (int i = 0; i < 4; ++i)
            a[i] = (MODE == 2) ? A[k * ST + r0 + i] : A[(r0 + i) * ST + k];
        #pragma unroll
        for (int j = 0; j < 4; ++j)
            b[j] = (MODE == 1) ? B[(c0 + j) * ST + k] : B[k * ST + c0 + j];
        #pragma unroll
        for (int i = 0; i < 4; ++i)
            #pragma unroll
            for (int j = 0; j < 4; ++j)
                acc[i][j] = fmaf(a[i], b[j], acc[i][j]);
    }
    #pragma unroll
    for (int i = 0; i < 4; ++i)
        #pragma unroll
        for (int j = 0; j < 4; ++j)
            C[(r0 + i) * ST + c0 + j] = acc[i][j];
}

// final M = F * F^T written straight to GMEM (float4 rows)
__device__ void gemm_ffT_out(const float* __restrict__ F,
                             float* __restrict__ out, int tid)
{
    const int r0 = (tid >> 4) * 4;
    const int c0 = (tid & 15) * 4;
    float acc[4][4];
    #pragma unroll
    for (int i = 0; i < 4; ++i)
        #pragma unroll
        for (int j = 0; j < 4; ++j) acc[i][j] = 0.f;

    #pragma unroll 4
    for (int k = 0; k < 64; ++k) {
        float a[4], b[4];
        #pragma unroll
        for (int i = 0; i < 4; ++i) a[i] = F[(r0 + i) * ST + k];
        #pragma unroll
        for (int j = 0; j < 4; ++j) b[j] = F[(c0 + j) * ST + k];
        #pragma unroll
        for (int i = 0; i < 4; ++i)
            #pragma unroll
            for (int j = 0; j < 4; ++j)
                acc[i][j] = fmaf(a[i], b[j], acc[i][j]);
    }
    #pragma unroll
    for (int i = 0; i < 4; ++i) {
        float4 v = make_float4(acc[i][0], acc[i][1], acc[i][2], acc[i][3]);
        *reinterpret_cast<float4*>(out + (r0 + i) * 64 + c0) = v;
    }
}

// ---------------------------------------------------------------------------
// main kernel: one CTA per batch element
// ---------------------------------------------------------------------------
__global__ void __launch_bounds__(256, 3)
spd_frechet_kernel(const float* __restrict__ xg,
                   const float* __restrict__ wg,
                   float* __restrict__ outg, int nsteps)
{
    extern __shared__ float sm[];
    float* MA  = sm;             // Jacobi working matrix / temps
    float* MV  = sm + MSZ;       // eigenvectors / temps
    float* MF  = sm + 2 * MSZ;   // F
    float* MFi = sm + 3 * MSZ;   // F^{-1}

    __shared__ int    spq[32];
    __shared__ float2 scs[32];
    __shared__ float  sd1[64], sd2[64];
    __shared__ float  st_[32];

    const int tid = threadIdx.x;
    const int b   = blockIdx.x;

    // t_n = w_n / cumsum(w)_n  (normalization of w cancels; w = weight^2)
    if (tid == 0) {
        float cum = 0.f;
        for (int k = 0; k < nsteps && k < 32; ++k) {
            float w2 = wg[k] * wg[k];
            cum += w2;
            st_[k] = w2 / cum;
        }
    }

    const float4* xb = reinterpret_cast<const float4*>(
        xg + (size_t)b * nsteps * 4096);

    // ---- load X_0 into MA ----
    #pragma unroll
    for (int it = 0; it < 4; ++it) {
        int idx4 = tid + it * 256;
        float4 v = xb[idx4];
        int flat = idx4 * 4;
        int i = flat >> 6, j = flat & 63;
        MA[i * ST + j + 0] = v.x;
        MA[i * ST + j + 1] = v.y;
        MA[i * ST + j + 2] = v.z;
        MA[i * ST + j + 3] = v.w;
    }
    __syncthreads();

    // ---- init: eigh(X0) -> F = V sqrt(E), Finv = E^{-1/2} V^T ----
    jacobi64(MA, MV, tid, spq, scs);
    if (tid < 64) {
        float e = fmaxf(MA[tid * ST + tid], EPSV);
        float s = sqrtf(e);
        sd1[tid] = s;
        sd2[tid] = 1.f / s;
    }
    __syncthreads();
    #pragma unroll
    for (int it = 0; it < 16; ++it) {
        int idx = tid + it * 256;
        int i = idx >> 6, j = idx & 63;
        MF[i * ST + j]  = MV[i * ST + j] * sd1[j];
        MFi[i * ST + j] = sd2[i] * MV[j * ST + i];
    }
    __syncthreads();

    // ---- scan steps n = 1..nsteps-1 ----
    #pragma unroll 1
    for (int n = 1; n < nsteps; ++n) {
        // load X_n into MA
        #pragma unroll
        for (int it = 0; it < 4; ++it) {
            int idx4 = tid + it * 256;
            float4 v = xb[n * 1024 + idx4];
            int flat = idx4 * 4;
            int i = flat >> 6, j = flat & 63;
            MA[i * ST + j + 0] = v.x;
            MA[i * ST + j + 1] = v.y;
            MA[i * ST + j + 2] = v.z;
            MA[i * ST + j + 3] = v.w;
        }
        __syncthreads();

        gemm64<0>(MFi, MA, MV, tid);   // T = Finv * X
        __syncthreads();
        gemm64<1>(MV, MFi, MA, tid);   // S = T * Finv^T
        __syncthreads();

        // symmetrize S
        float tmp[16];
        #pragma unroll
        for (int it = 0; it < 16; ++it) {
            int idx = tid + it * 256;
            int i = idx >> 6, j = idx & 63;
            tmp[it] = 0.5f * (MA[i * ST + j] + MA[j * ST + i]);
        }
        __syncthreads();
        #pragma unroll
        for (int it = 0; it < 16; ++it) {
            int idx = tid + it * 256;
            int i = idx >> 6, j = idx & 63;
            MA[i * ST + j] = tmp[it];
        }
        __syncthreads();

        // eigh(S)
        jacobi64(MA, MV, tid, spq, scs);

        // d1 = E^{t/2}, d2 = E^{-t/2}
        float ht = 0.5f * st_[n];
        if (tid < 64) {
            float e = fmaxf(MA[tid * ST + tid], EPSV);
            float p = powf(e, ht);
            sd1[tid] = p;
            sd2[tid] = 1.f / p;
        }
        __syncthreads();

        // F' = (F * V2) * diag(d1)
        gemm64<0>(MF, MV, MA, tid);
        __syncthreads();
        #pragma unroll
        for (int it = 0; it < 16; ++it) {
            int idx = tid + it * 256;
            int i = idx >> 6, j = idx & 63;
            MF[i * ST + j] = MA[i * ST + j] * sd1[j];
        }
        __syncthreads();

        // Finv' = diag(d2) * (V2^T * Finv)
        gemm64<2>(MV, MFi, MA, tid);
        __syncthreads();
        #pragma unroll
        for (int it = 0; it < 16; ++it) {
            int idx = tid + it * 256;
            int i = idx >> 6, j = idx & 63;
            MFi[i * ST + j] = sd2[i] * MA[i * ST + j];
        }
        __syncthreads();
    }

    // ---- M = F * F^T -> output ----
    gemm_ffT_out(MF, outg + (size_t)b * 4096, tid);
}

// ---------------------------------------------------------------------------
extern "C" void kernel_launch(void* const* d_in, const int* in_sizes, int n_in,
                              void* d_out, int out_size)
{
    const float* x = (const float*)d_in[0];
    const float* w = (const float*)d_in[1];
    int sx = in_sizes[0], sw = in_sizes[1];
    if (n_in >= 2 && sx < sw) {  // defensive: x is the big tensor
        const float* t = x; x = w; w = t;
        int ts = sx; sx = sw; sw = ts;
    }
    const int nsteps = sw;                    // N = 16
    const int B = sx / (nsteps * 64 * 64);    // 512
    float* out = (float*)d_out;

    const int smem_bytes = 4 * MSZ * sizeof(float);  // 66,560 B
    cudaFuncSetAttribute(spd_frechet_kernel,
                         cudaFuncAttributeMaxDynamicSharedMemorySize,
                         smem_bytes);
    spd_frechet_kernel<<<B, 256, smem_bytes>>>(x, w, out, nsteps);
}

// round 10
// speedup vs baseline: 1.0498x; 1.0005x over previous
#include <cuda_runtime.h>
#include <math.h>

#define ST     65
#define MSZ    (64*ST)
#define EPSV   1e-10f
#define NSWEEP 7

// ---------------------------------------------------------------------------
// round-robin tournament pairing: 63 rounds x 32 disjoint pairs covering all
// unordered pairs of {0..63}
// ---------------------------------------------------------------------------
__device__ __forceinline__ int2 pair_for(int r, int k) {
    int p, q;
    if (k == 0) {
        p = 63;
        q = r;                 // r in [0,62] already < 63
    } else {
        p = r + k;       if (p >= 63) p -= 63;
        q = r + 63 - k;  if (q >= 63) q -= 63;
    }
    if (p > q) { int t = p; p = q; q = t; }
    return make_int2(p, q);
}

// ---------------------------------------------------------------------------
// parallel cyclic Jacobi eigensolver for symmetric 64x64 in SMEM.
// Fixed NSWEEP sweeps — no data-dependent control flow, no early exit.
// On exit: diag(A) = eigenvalues, V = eigenvectors (columns).
// 256 threads.
// ---------------------------------------------------------------------------
__device__ void jacobi64(float* __restrict__ A, float* __restrict__ V, int tid,
                         int* __restrict__ spq, float2* __restrict__ scs)
{
    // V = I
    #pragma unroll
    for (int it = 0; it < 16; ++it) {
        int idx = tid + it * 256;
        int i = idx >> 6, j = idx & 63;
        V[i * ST + j] = (i == j) ? 1.f : 0.f;
    }
    __syncthreads();

    #pragma unroll 1
    for (int sweep = 0; sweep < NSWEEP; ++sweep) {
        #pragma unroll 1
        for (int r = 0; r < 63; ++r) {
            // --- rotation generation (warp 0 only) ---
            if (tid < 32) {
                int2 pq = pair_for(r, tid);
                int p = pq.x, q = pq.y;
                float app = A[p * ST + p];
                float aqq = A[q * ST + q];
                float apq = A[p * ST + q];
                float c = 1.f, s = 0.f;
                if (apq * apq > 1e-10f * app * aqq) {
                    float tau = (aqq - app) / (2.f * apq);
                    float tf  = copysignf(1.f, tau) /
                                (fabsf(tau) + sqrtf(fmaf(tau, tau, 1.f)));
                    c = 1.f / sqrtf(fmaf(tf, tf, 1.f));
                    s = tf * c;
                }
                spq[tid] = p | (q << 8);
                scs[tid] = make_float2(c, s);
            }
            __syncthreads();

            // --- row phase: A <- J^T A ---
            // w = tid + it*256 : k = w>>6 (uniform per warp), j = w&63
            #pragma unroll
            for (int it = 0; it < 8; ++it) {
                int w = tid + it * 256;
                int k = w >> 6, j = w & 63;
                float2 cs = scs[k];
                if (cs.y != 0.f) {
                    int pq = spq[k];
                    int p = pq & 255, q = pq >> 8;
                    float ap = A[p * ST + j], aq = A[q * ST + j];
                    A[p * ST + j] = fmaf(cs.x, ap, -cs.y * aq);
                    A[q * ST + j] = fmaf(cs.y, ap,  cs.x * aq);
                }
            }
            __syncthreads();

            // --- col phase: A <- A J, V <- V J ---
            #pragma unroll
            for (int it = 0; it < 8; ++it) {
                int w = tid + it * 256;
                int k = w >> 6, i = w & 63;
                float2 cs = scs[k];
                if (cs.y != 0.f) {
                    int pq = spq[k];
                    int p = pq & 255, q = pq >> 8;
                    int ip = i * ST + p, iq = i * ST + q;
                    float ap = A[ip], aq = A[iq];
                    A[ip] = fmaf(cs.x, ap, -cs.y * aq);
                    A[iq] = fmaf(cs.y, ap,  cs.x * aq);
                    float vp = V[ip], vq = V[iq];
                    V[ip] = fmaf(cs.x, vp, -cs.y * vq);
                    V[iq] = fmaf(cs.y, vp,  cs.x * vq);
                }
            }
            __syncthreads();
        }
    }
}

// ---------------------------------------------------------------------------
// 64x64x64 SMEM GEMM, 256 threads, 4x4 register tile per thread.
// MODE 0: C = A*B    MODE 1: C = A*B^T    MODE 2: C = A^T*B
// ---------------------------------------------------------------------------
template<int MODE>
__device__ void gemm64(const float* __restrict__ A, const float* __restrict__ B,
                       float* __restrict__ C, int tid)
{
    const int r0 = (tid >> 4) * 4;
    const int c0 = (tid & 15) * 4;
    float acc[4][4];
    #pragma unroll
    for (int i = 0; i < 4; ++i)
        #pragma unroll
        for (int j = 0; j < 4; ++j) acc[i][j] = 0.f;

    #pragma unroll 4
    for (int k = 0; k < 64; ++k) {
        float a[4], b[4];
        #pragma unroll
        for (int i = 0; i < 4; ++i)
            a[i] = (MODE == 2) ? A[k * ST + r0 + i] : A[(r0 + i) * ST + k];
        #pragma unroll
        for (int j = 0; j < 4; ++j)
            b[j] = (MODE == 1) ? B[(c0 + j) * ST + k] : B[k * ST + c0 + j];
        #pragma unroll
        for (int i = 0; i < 4; ++i)
            #pragma unroll
            for (int j = 0; j < 4; ++j)
                acc[i][j] = fmaf(a[i], b[j], acc[i][j]);
    }
    #pragma unroll
    for (int i = 0; i < 4; ++i)
        #pragma unroll
        for (int j = 0; j < 4; ++j)
            C[(r0 + i) * ST + c0 + j] = acc[i][j];
}

// final M = F * F^T written straight to GMEM (float4 rows)
__device__ void gemm_ffT_out(const float* __restrict__ F,
                             float* __restrict__ out, int tid)
{
    const int r0 = (tid >> 4) * 4;
    const int c0 = (tid & 15) * 4;
    float acc[4][4];
    #pragma unroll
    for (int i = 0; i < 4; ++i)
        #pragma unroll
        for (int j = 0; j < 4; ++j) acc[i][j] = 0.f;

    #pragma unroll 4
    for (int k = 0; k < 64; ++k) {
        float a[4], b[4];
        #pragma unroll
        for (int i = 0; i < 4; ++i) a[i] = F[(r0 + i) * ST + k];
        #pragma unroll
        for (int j = 0; j < 4; ++j) b[j] = F[(c0 + j) * ST + k];
        #pragma unroll
        for (int i = 0; i < 4; ++i)
            #pragma unroll
            for (int j = 0; j < 4; ++j)
                acc[i][j] = fmaf(a[i], b[j], acc[i][j]);
    }
    #pragma unroll
    for (int i = 0; i < 4; ++i) {
        float4 v = make_float4(acc[i][0], acc[i][1], acc[i][2], acc[i][3]);
        *reinterpret_cast<float4*>(out + (r0 + i) * 64 + c0) = v;
    }
}

// ---------------------------------------------------------------------------
// main kernel: one CTA per batch element
// ---------------------------------------------------------------------------
__global__ void __launch_bounds__(256, 3)
spd_frechet_kernel(const float* __restrict__ xg,
                   const float* __restrict__ wg,
                   float* __restrict__ outg, int nsteps)
{
    extern __shared__ float sm[];
    float* MA  = sm;             // Jacobi working matrix / temps
    float* MV  = sm + MSZ;       // eigenvectors / temps
    float* MF  = sm + 2 * MSZ;   // F
    float* MFi = sm + 3 * MSZ;   // F^{-1}

    __shared__ int    spq[32];
    __shared__ float2 scs[32];
    __shared__ float  sd1[64], sd2[64];
    __shared__ float  st_[32];

    const int tid = threadIdx.x;
    const int b   = blockIdx.x;

    // t_n = w_n / cumsum(w)_n  (normalization of w cancels; w = weight^2)
    if (tid == 0) {
        float cum = 0.f;
        for (int k = 0; k < nsteps && k < 32; ++k) {
            float w2 = wg[k] * wg[k];
            cum += w2;
            st_[k] = w2 / cum;
        }
    }

    const float4* xb = reinterpret_cast<const float4*>(
        xg + (size_t)b * nsteps * 4096);

    // ---- load X_0 into MA ----
    #pragma unroll
    for (int it = 0; it < 4; ++it) {
        int idx4 = tid + it * 256;
        float4 v = xb[idx4];
        int flat = idx4 * 4;
        int i = flat >> 6, j = flat & 63;
        MA[i * ST + j + 0] = v.x;
        MA[i * ST + j + 1] = v.y;
        MA[i * ST + j + 2] = v.z;
        MA[i * ST + j + 3] = v.w;
    }
    __syncthreads();

    // ---- init: eigh(X0) -> F = V sqrt(E), Finv = E^{-1/2} V^T ----
    jacobi64(MA, MV, tid, spq, scs);
    if (tid < 64) {
        float e = fmaxf(MA[tid * ST + tid], EPSV);
        float s = sqrtf(e);
        sd1[tid] = s;
        sd2[tid] = 1.f / s;
    }
    __syncthreads();
    #pragma unroll
    for (int it = 0; it < 16; ++it) {
        int idx = tid + it * 256;
        int i = idx >> 6, j = idx & 63;
        MF[i * ST + j]  = MV[i * ST + j] * sd1[j];
        MFi[i * ST + j] = sd2[i] * MV[j * ST + i];
    }
    __syncthreads();

    // ---- scan steps n = 1..nsteps-1 ----
    #pragma unroll 1
    for (int n = 1; n < nsteps; ++n) {
        // load X_n into MA
        #pragma unroll
        for (int it = 0; it < 4; ++it) {
            int idx4 = tid + it * 256;
            float4 v = xb[n * 1024 + idx4];
            int flat = idx4 * 4;
            int i = flat >> 6, j = flat & 63;
            MA[i * ST + j + 0] = v.x;
            MA[i * ST + j + 1] = v.y;
            MA[i * ST + j + 2] = v.z;
            MA[i * ST + j + 3] = v.w;
        }
        __syncthreads();

        gemm64<0>(MFi, MA, MV, tid);   // T = Finv * X
        __syncthreads();
        gemm64<1>(MV, MFi, MA, tid);   // S = T * Finv^T
        __syncthreads();

        // symmetrize S
        float tmp[16];
        #pragma unroll
        for (int it = 0; it < 16; ++it) {
            int idx = tid + it * 256;
            int i = idx >> 6, j = idx & 63;
            tmp[it] = 0.5f * (MA[i * ST + j] + MA[j * ST + i]);
        }
        __syncthreads();
        #pragma unroll
        for (int it = 0; it < 16; ++it) {
            int idx = tid + it * 256;
            int i = idx >> 6, j = idx & 63;
            MA[i * ST + j] = tmp[it];
        }
        __syncthreads();

        // eigh(S)
        jacobi64(MA, MV, tid, spq, scs);

        // d1 = E^{t/2}, d2 = E^{-t/2}
        float ht = 0.5f * st_[n];
        if (tid < 64) {
            float e = fmaxf(MA[tid * ST + tid], EPSV);
            float p = powf(e, ht);
            sd1[tid] = p;
            sd2[tid] = 1.f / p;
        }
        __syncthreads();

        // F' = (F * V2) * diag(d1)
        gemm64<0>(MF, MV, MA, tid);
        __syncthreads();
        #pragma unroll
        for (int it = 0; it < 16; ++it) {
            int idx = tid + it * 256;
            int i = idx >> 6, j = idx & 63;
            MF[i * ST + j] = MA[i * ST + j] * sd1[j];
        }
        __syncthreads();

        // Finv' = diag(d2) * (V2^T * Finv)
        gemm64<2>(MV, MFi, MA, tid);
        __syncthreads();
        #pragma unroll
        for (int it = 0; it < 16; ++it) {
            int idx = tid + it * 256;
            int i = idx >> 6, j = idx & 63;
            MFi[i * ST + j] = sd2[i] * MA[i * ST + j];
        }
        __syncthreads();
    }

    // ---- M = F * F^T -> output ----
    gemm_ffT_out(MF, outg + (size_t)b * 4096, tid);
}

// ---------------------------------------------------------------------------
extern "C" void kernel_launch(void* const* d_in, const int* in_sizes, int n_in,
                              void* d_out, int out_size)
{
    const float* x = (const float*)d_in[0];
    const float* w = (const float*)d_in[1];
    int sx = in_sizes[0], sw = in_sizes[1];
    if (n_in >= 2 && sx < sw) {  // defensive: x is the big tensor
        const float* t = x; x = w; w = t;
        int ts = sx; sx = sw; sw = ts;
    }
    const int nsteps = sw;                    // N = 16
    const int B = sx / (nsteps * 64 * 64);    // 512
    float* out = (float*)d_out;

    const int smem_bytes = 4 * MSZ * sizeof(float);  // 66,560 B
    cudaFuncSetAttribute(spd_frechet_kernel,
                         cudaFuncAttributeMaxDynamicSharedMemorySize,
                         smem_bytes);
    spd_frechet_kernel<<<B, 256, smem_bytes>>>(x, w, out, nsteps);
}

// round 11
// speedup vs baseline: 1.0502x; 1.0004x over previous
#include <cuda_runtime.h>
#include <math.h>

#define ST     65
#define MSZ    (64*ST)
#define EPSV   1e-10f
#define NSWEEP 7

// ---------------------------------------------------------------------------
// round-robin tournament pairing: 63 rounds x 32 disjoint pairs covering all
// unordered pairs of {0..63}
// ---------------------------------------------------------------------------
__device__ __forceinline__ int2 pair_for(int r, int k) {
    int p, q;
    if (k == 0) {
        p = 63;
        q = r;                 // r in [0,62] already < 63
    } else {
        p = r + k;       if (p >= 63) p -= 63;
        q = r + 63 - k;  if (q >= 63) q -= 63;
    }
    if (p > q) { int t = p; p = q; q = t; }
    return make_int2(p, q);
}

// ---------------------------------------------------------------------------
// parallel cyclic Jacobi eigensolver for symmetric 64x64 in SMEM.
// Fixed NSWEEP sweeps — no data-dependent control flow, no early exit.
// On exit: diag(A) = eigenvalues, V = eigenvectors (columns).
// 256 threads.
// ---------------------------------------------------------------------------
__device__ void jacobi64(float* __restrict__ A, float* __restrict__ V, int tid,
                         int* __restrict__ spq, float2* __restrict__ scs)
{
    // V = I
    #pragma unroll
    for (int it = 0; it < 16; ++it) {
        int idx = tid + it * 256;
        int i = idx >> 6, j = idx & 63;
        V[i * ST + j] = (i == j) ? 1.f : 0.f;
    }
    __syncthreads();

    #pragma unroll 1
    for (int sweep = 0; sweep < NSWEEP; ++sweep) {
        #pragma unroll 1
        for (int r = 0; r < 63; ++r) {
            // --- rotation generation (warp 0 only) ---
            if (tid < 32) {
                int2 pq = pair_for(r, tid);
                int p = pq.x, q = pq.y;
                float app = A[p * ST + p];
                float aqq = A[q * ST + q];
                float apq = A[p * ST + q];
                float c = 1.f, s = 0.f;
                if (apq * apq > 1e-10f * app * aqq) {
                    float tau = (aqq - app) / (2.f * apq);
                    float tf  = copysignf(1.f, tau) /
                                (fabsf(tau) + sqrtf(fmaf(tau, tau, 1.f)));
                    c = 1.f / sqrtf(fmaf(tf, tf, 1.f));
                    s = tf * c;
                }
                spq[tid] = p | (q << 8);
                scs[tid] = make_float2(c, s);
            }
            __syncthreads();

            // --- row phase: A <- J^T A ---
            // w = tid + it*256 : k = w>>6 (uniform per warp), j = w&63
            #pragma unroll
            for (int it = 0; it < 8; ++it) {
                int w = tid + it * 256;
                int k = w >> 6, j = w & 63;
                float2 cs = scs[k];
                if (cs.y != 0.f) {
                    int pq = spq[k];
                    int p = pq & 255, q = pq >> 8;
                    float ap = A[p * ST + j], aq = A[q * ST + j];
                    A[p * ST + j] = fmaf(cs.x, ap, -cs.y * aq);
                    A[q * ST + j] = fmaf(cs.y, ap,  cs.x * aq);
                }
            }
            __syncthreads();

            // --- col phase: A <- A J, V <- V J ---
            #pragma unroll
            for (int it = 0; it < 8; ++it) {
                int w = tid + it * 256;
                int k = w >> 6, i = w & 63;
                float2 cs = scs[k];
                if (cs.y != 0.f) {
                    int pq = spq[k];
                    int p = pq & 255, q = pq >> 8;
                    int ip = i * ST + p, iq = i * ST + q;
                    float ap = A[ip], aq = A[iq];
                    A[ip] = fmaf(cs.x, ap, -cs.y * aq);
                    A[iq] = fmaf(cs.y, ap,  cs.x * aq);
                    float vp = V[ip], vq = V[iq];
                    V[ip] = fmaf(cs.x, vp, -cs.y * vq);
                    V[iq] = fmaf(cs.y, vp,  cs.x * vq);
                }
            }
            __syncthreads();
        }
    }
}

// ---------------------------------------------------------------------------
// 64x64x64 SMEM GEMM, 256 threads, 4x4 register tile per thread.
// MODE 0: C = A*B    MODE 1: C = A*B^T    MODE 2: C = A^T*B
// ---------------------------------------------------------------------------
template<int MODE>
__device__ void gemm64(const float* __restrict__ A, const float* __restrict__ B,
                       float* __restrict__ C, int tid)
{
    const int r0 = (tid >> 4) * 4;
    const int c0 = (tid & 15) * 4;
    float acc[4][4];
    #pragma unroll
    for (int i = 0; i < 4; ++i)
        #pragma unroll
        for (int j = 0; j < 4; ++j) acc[i][j] = 0.f;

    #pragma unroll 4
    for (int k = 0; k < 64; ++k) {
        float a[4], b[4];
        #pragma unroll
        for (int i = 0; i < 4; ++i)
            a[i] = (MODE == 2) ? A[k * ST + r0 + i] : A[(r0 + i) * ST + k];
        #pragma unroll
        for (int j = 0; j < 4; ++j)
            b[j] = (MODE == 1) ? B[(c0 + j) * ST + k] : B[k * ST + c0 + j];
        #pragma unroll
        for (int i = 0; i < 4; ++i)
            #pragma unroll
            for (int j = 0; j < 4; ++j)
                acc[i][j] = fmaf(a[i], b[j], acc[i][j]);
    }
    #pragma unroll
    for (int i = 0; i < 4; ++i)
        #pragma unroll
        for (int j = 0; j < 4; ++j)
            C[(r0 + i) * ST + c0 + j] = acc[i][j];
}

// final M = F * F^T written straight to GMEM (float4 rows)
__device__ void gemm_ffT_out(const float* __restrict__ F,
                             float* __restrict__ out, int tid)
{
    const int r0 = (tid >> 4) * 4;
    const int c0 = (tid & 15) * 4;
    float acc[4][4];
    #pragma unroll
    for (int i = 0; i < 4; ++i)
        #pragma unroll
        for (int j = 0; j < 4; ++j) acc[i][j] = 0.f;

    #pragma unroll 4
    for (int k = 0; k < 64; ++k) {
        float a[4], b[4];
        #pragma unroll
        for (int i = 0; i < 4; ++i) a[i] = F[(r0 + i) * ST + k];
        #pragma unroll
        for (int j = 0; j < 4; ++j) b[j] = F[(c0 + j) * ST + k];
        #pragma unroll
        for (int i = 0; i < 4; ++i)
            #pragma unroll
            for (int j = 0; j < 4; ++j)
                acc[i][j] = fmaf(a[i], b[j], acc[i][j]);
    }
    #pragma unroll
    for (int i = 0; i < 4; ++i) {
        float4 v = make_float4(acc[i][0], acc[i][1], acc[i][2], acc[i][3]);
        *reinterpret_cast<float4*>(out + (r0 + i) * 64 + c0) = v;
    }
}

// ---------------------------------------------------------------------------
// main kernel: one CTA per batch element
// ---------------------------------------------------------------------------
__global__ void __launch_bounds__(256, 3)
spd_frechet_kernel(const float* __restrict__ xg,
                   const float* __restrict__ wg,
                   float* __restrict__ outg, int nsteps)
{
    extern __shared__ float sm[];
    float* MA  = sm;             // Jacobi working matrix / temps
    float* MV  = sm + MSZ;       // eigenvectors / temps
    float* MF  = sm + 2 * MSZ;   // F
    float* MFi = sm + 3 * MSZ;   // F^{-1}

    __shared__ int    spq[32];
    __shared__ float2 scs[32];
    __shared__ float  sd1[64], sd2[64];
    __shared__ float  st_[32];

    const int tid = threadIdx.x;
    const int b   = blockIdx.x;

    // t_n = w_n / cumsum(w)_n  (normalization of w cancels; w = weight^2)
    if (tid == 0) {
        float cum = 0.f;
        for (int k = 0; k < nsteps && k < 32; ++k) {
            float w2 = wg[k] * wg[k];
            cum += w2;
            st_[k] = w2 / cum;
        }
    }

    const float4* xb = reinterpret_cast<const float4*>(
        xg + (size_t)b * nsteps * 4096);

    // ---- load X_0 into MA ----
    #pragma unroll
    for (int it = 0; it < 4; ++it) {
        int idx4 = tid + it * 256;
        float4 v = xb[idx4];
        int flat = idx4 * 4;
        int i = flat >> 6, j = flat & 63;
        MA[i * ST + j + 0] = v.x;
        MA[i * ST + j + 1] = v.y;
        MA[i * ST + j + 2] = v.z;
        MA[i * ST + j + 3] = v.w;
    }
    __syncthreads();

    // ---- init: eigh(X0) -> F = V sqrt(E), Finv = E^{-1/2} V^T ----
    jacobi64(MA, MV, tid, spq, scs);
    if (tid < 64) {
        float e = fmaxf(MA[tid * ST + tid], EPSV);
        float s = sqrtf(e);
        sd1[tid] = s;
        sd2[tid] = 1.f / s;
    }
    __syncthreads();
    #pragma unroll
    for (int it = 0; it < 16; ++it) {
        int idx = tid + it * 256;
        int i = idx >> 6, j = idx & 63;
        MF[i * ST + j]  = MV[i * ST + j] * sd1[j];
        MFi[i * ST + j] = sd2[i] * MV[j * ST + i];
    }
    __syncthreads();

    // ---- scan steps n = 1..nsteps-1 ----
    #pragma unroll 1
    for (int n = 1; n < nsteps; ++n) {
        // load X_n into MA
        #pragma unroll
        for (int it = 0; it < 4; ++it) {
            int idx4 = tid + it * 256;
            float4 v = xb[n * 1024 + idx4];
            int flat = idx4 * 4;
            int i = flat >> 6, j = flat & 63;
            MA[i * ST + j + 0] = v.x;
            MA[i * ST + j + 1] = v.y;
            MA[i * ST + j + 2] = v.z;
            MA[i * ST + j + 3] = v.w;
        }
        __syncthreads();

        gemm64<0>(MFi, MA, MV, tid);   // T = Finv * X
        __syncthreads();
        gemm64<1>(MV, MFi, MA, tid);   // S = T * Finv^T
        __syncthreads();

        // symmetrize S
        float tmp[16];
        #pragma unroll
        for (int it = 0; it < 16; ++it) {
            int idx = tid + it * 256;
            int i = idx >> 6, j = idx & 63;
            tmp[it] = 0.5f * (MA[i * ST + j] + MA[j * ST + i]);
        }
        __syncthreads();
        #pragma unroll
        for (int it = 0; it < 16; ++it) {
            int idx = tid + it * 256;
            int i = idx >> 6, j = idx & 63;
            MA[i * ST + j] = tmp[it];
        }
        __syncthreads();

        // eigh(S)
        jacobi64(MA, MV, tid, spq, scs);

        // d1 = E^{t/2}, d2 = E^{-t/2}
        float ht = 0.5f * st_[n];
        if (tid < 64) {
            float e = fmaxf(MA[tid * ST + tid], EPSV);
            float p = powf(e, ht);
            sd1[tid] = p;
            sd2[tid] = 1.f / p;
        }
        __syncthreads();

        // F' = (F * V2) * diag(d1)
        gemm64<0>(MF, MV, MA, tid);
        __syncthreads();
        #pragma unroll
        for (int it = 0; it < 16; ++it) {
            int idx = tid + it * 256;
            int i = idx >> 6, j = idx & 63;
            MF[i * ST + j] = MA[i * ST + j] * sd1[j];
        }
        __syncthreads();

        // Finv' = diag(d2) * (V2^T * Finv)
        gemm64<2>(MV, MFi, MA, tid);
        __syncthreads();
        #pragma unroll
        for (int it = 0; it < 16; ++it) {
            int idx = tid + it * 256;
            int i = idx >> 6, j = idx & 63;
            MFi[i * ST + j] = sd2[i] * MA[i * ST + j];
        }
        __syncthreads();
    }

    // ---- M = F * F^T -> output ----
    gemm_ffT_out(MF, outg + (size_t)b * 4096, tid);
}

// ---------------------------------------------------------------------------
extern "C" void kernel_launch(void* const* d_in, const int* in_sizes, int n_in,
                              void* d_out, int out_size)
{
    const float* x = (const float*)d_in[0];
    const float* w = (const float*)d_in[1];
    int sx = in_sizes[0], sw = in_sizes[1];
    if (n_in >= 2 && sx < sw) {  // defensive: x is the big tensor
        const float* t = x; x = w; w = t;
        int ts = sx; sx = sw; sw = ts;
    }
    const int nsteps = sw;                    // N = 16
    const int B = sx / (nsteps * 64 * 64);    // 512
    float* out = (float*)d_out;

    const int smem_bytes = 4 * MSZ * sizeof(float);  // 66,560 B
    cudaFuncSetAttribute(spd_frechet_kernel,
                         cudaFuncAttributeMaxDynamicSharedMemorySize,
                         smem_bytes);
    spd_frechet_kernel<<<B, 256, smem_bytes>>>(x, w, out, nsteps);
}